// round 14
// baseline (speedup 1.0000x reference)
#include <cuda_runtime.h>
#include <cuda_bf16.h>
#include <stdint.h>
#include <stddef.h>

#define BB 256
#define TT 512
#define HH 128
#define GG 384   /* 3*H */

typedef unsigned long long ull;

// ---------------- scratch (device globals; no allocation allowed) ----------
__device__ float g_xw0f[(size_t)BB * TT * GG];
__device__ float g_xw0b[(size_t)BB * TT * GG];
__device__ float g_xw1f[(size_t)BB * TT * GG];
__device__ __nv_bfloat16 g_h0hi[(size_t)BB * TT * 2 * HH];
__device__ __nv_bfloat16 g_h0lo[(size_t)BB * TT * 2 * HH];
__device__ float g_h1f [BB * HH];
__device__ __nv_bfloat16 g_xhi[(size_t)BB * TT * 64];
__device__ __nv_bfloat16 g_xlo[(size_t)BB * TT * 64];
__device__ __nv_bfloat16 g_w0fhi[GG * 64],  g_w0flo[GG * 64];
__device__ __nv_bfloat16 g_w0bhi[GG * 64],  g_w0blo[GG * 64];
__device__ __nv_bfloat16 g_w1fhi[GG * 256], g_w1flo[GG * 256];

// ---------------- small helpers --------------------------------------------
__device__ __forceinline__ void ffma2(ull &d, ull a, ull b) {
    asm("fma.rn.f32x2 %0, %1, %2, %0;" : "+l"(d) : "l"(a), "l"(b));
}
__device__ __forceinline__ float hsum2(ull v) {
    float lo, hi;
    asm("mov.b64 {%0,%1}, %2;" : "=f"(lo), "=f"(hi) : "l"(v));
    return lo + hi;
}
__device__ __forceinline__ float sigf(float x)     { return 1.f / (1.f + __expf(-x)); }
__device__ __forceinline__ float tanhfast(float x) { return 2.f / (1.f + __expf(-2.f * x)) - 1.f; }

__device__ __forceinline__ void cp_async16(void* smem, const void* gmem) {
    uint32_t s = (uint32_t)__cvta_generic_to_shared(smem);
    asm volatile("cp.async.cg.shared.global [%0], [%1], 16;" :: "r"(s), "l"(gmem));
}
__device__ __forceinline__ void cp_async4(void* smem, const void* gmem) {
    uint32_t s = (uint32_t)__cvta_generic_to_shared(smem);
    asm volatile("cp.async.ca.shared.global [%0], [%1], 4;" :: "r"(s), "l"(gmem));
}
__device__ __forceinline__ void cp_commit() { asm volatile("cp.async.commit_group;"); }
template <int N>
__device__ __forceinline__ void cp_wait() { asm volatile("cp.async.wait_group %0;" :: "n"(N)); }

__device__ __forceinline__ uint32_t smem_u32(const void* p) {
    return (uint32_t)__cvta_generic_to_shared(p);
}

__device__ __forceinline__ void ldmat_x4(uint32_t &r0, uint32_t &r1, uint32_t &r2,
                                         uint32_t &r3, uint32_t addr) {
    asm volatile("ldmatrix.sync.aligned.m8n8.x4.shared.b16 {%0,%1,%2,%3}, [%4];"
                 : "=r"(r0), "=r"(r1), "=r"(r2), "=r"(r3) : "r"(addr));
}
__device__ __forceinline__ void mma_bf16(float c[4], const uint32_t a[4],
                                         const uint32_t b[2]) {
    asm volatile(
        "mma.sync.aligned.m16n8k16.row.col.f32.bf16.bf16.f32 "
        "{%0,%1,%2,%3}, {%4,%5,%6,%7}, {%8,%9}, {%0,%1,%2,%3};"
        : "+f"(c[0]), "+f"(c[1]), "+f"(c[2]), "+f"(c[3])
        : "r"(a[0]), "r"(a[1]), "r"(a[2]), "r"(a[3]), "r"(b[0]), "r"(b[1]));
}

// ---------------- fused fp32 -> bf16 hi/lo split (4 tensors, 1 launch) -----
__global__ void split_bf16_multi(
    const float* __restrict__ s0, __nv_bfloat16* __restrict__ h0, __nv_bfloat16* __restrict__ l0, int n0,
    const float* __restrict__ s1, __nv_bfloat16* __restrict__ h1, __nv_bfloat16* __restrict__ l1, int n1,
    const float* __restrict__ s2, __nv_bfloat16* __restrict__ h2, __nv_bfloat16* __restrict__ l2, int n2,
    const float* __restrict__ s3, __nv_bfloat16* __restrict__ h3, __nv_bfloat16* __restrict__ l3, int n3) {
    int i = blockIdx.x * blockDim.x + threadIdx.x;
    const float* s; __nv_bfloat16 *hi, *lo;
    if (i < n0)                { s = s0 + i; hi = h0 + i; lo = l0 + i; }
    else if (i < n0 + n1)      { int j = i - n0;           s = s1 + j; hi = h1 + j; lo = l1 + j; }
    else if (i < n0 + n1 + n2) { int j = i - n0 - n1;      s = s2 + j; hi = h2 + j; lo = l2 + j; }
    else if (i < n0 + n1 + n2 + n3) { int j = i - n0 - n1 - n2; s = s3 + j; hi = h3 + j; lo = l3 + j; }
    else return;
    float v = *s;
    __nv_bfloat16 h = __float2bfloat16(v);
    *hi = h;
    *lo = __float2bfloat16(v - __bfloat162float(h));
}

// ---------------- HMMA GEMM: C[M,384] = A[M,K] @ W[384,K]^T + bias ---------
// bf16x3 split with panel-reuse term order per k-chunk:
//   tau0: (Ahi, Blo)   tau1: (Ahi, Bhi)   tau2: (Alo, Bhi)
// A stages at tau in {0,2}, B at tau in {0,1} -> 4 panels/chunk (was 6),
// cutting L2 traffic 33%. A and B live in independent 3-slot rings (panels
// advance +2 per 3 iterations -> staged slot never collides with the two
// in-flight compute slots). Pipeline keeps 2 commit-groups in flight.
template <int K, int NSETS>
__global__ void __launch_bounds__(256, 2) gemm_hmma(
    const __nv_bfloat16* __restrict__ Ahi, const __nv_bfloat16* __restrict__ Alo,
    const __nv_bfloat16* __restrict__ W0hi, const __nv_bfloat16* __restrict__ W0lo,
    const float* __restrict__ b0, float* __restrict__ C0,
    const __nv_bfloat16* __restrict__ W1hi, const __nv_bfloat16* __restrict__ W1lo,
    const float* __restrict__ b1, float* __restrict__ C1) {
    constexpr int NCH = K / 64;
    constexpr int NIT = 3 * NCH;
    constexpr int LD  = 72;
    constexpr int TILE = 128 * LD;   // elems per panel (18KB)

    extern __shared__ __nv_bfloat16 smh[];
    __nv_bfloat16* Ar = smh;              // [3][TILE]
    __nv_bfloat16* Br = smh + 3 * TILE;   // [3][TILE]

    const int tid = threadIdx.x;
    const int wid = tid >> 5, lane = tid & 31;

    int bx = blockIdx.x;
    const __nv_bfloat16 *Whi = W0hi, *Wlo = W0lo;
    const float* bias = b0; float* C = C0;
    if (NSETS == 2 && bx >= 3) { Whi = W1hi; Wlo = W1lo; bias = b1; C = C1; bx -= 3; }
    const int n0 = bx * 128;
    const int m0 = blockIdx.y * 128;

    // stage k-th A panel (even=hi, odd=lo; chunk=k>>1) into slot k%3
    auto stageA = [&](int k) {
        const __nv_bfloat16* src = (k & 1) ? Alo : Ahi;
        const int ch = k >> 1, slot = k % 3;
        #pragma unroll
        for (int r = 0; r < 4; r++) {
            int idx = tid + r * 256;
            int row = idx >> 3, c = (idx & 7) * 8;
            cp_async16(&Ar[slot * TILE + row * LD + c],
                       &src[(size_t)(m0 + row) * K + ch * 64 + c]);
        }
    };
    // stage k-th B panel (even=lo, odd=hi; chunk=k>>1) into slot k%3
    auto stageB = [&](int k) {
        const __nv_bfloat16* src = (k & 1) ? Whi : Wlo;
        const int ch = k >> 1, slot = k % 3;
        #pragma unroll
        for (int r = 0; r < 4; r++) {
            int idx = tid + r * 256;
            int row = idx >> 3, c = (idx & 7) * 8;
            cp_async16(&Br[slot * TILE + row * LD + c],
                       &src[(size_t)(n0 + row) * K + ch * 64 + c]);
        }
    };
    // stage event j (tau = j%3): tau0 -> A(2j')+B(2j'); tau1 -> B(2j'+1); tau2 -> A(2j'+1)
    auto stageEvent = [&](int j) {
        const int jp = j / 3, tau = j % 3;
        if (tau == 0)      { stageA(2 * jp); stageB(2 * jp); }
        else if (tau == 1) { stageB(2 * jp + 1); }
        else               { stageA(2 * jp + 1); }
        cp_commit();
    };

    stageEvent(0);
    if (NIT > 1) stageEvent(1);
    if (NIT > 2) stageEvent(2);

    const int wm = wid >> 1, wn = wid & 1;
    const int lr = lane & 7, sel = lane >> 3;
    const int a_ro = (sel & 1) * 8 + lr, a_co = (sel >> 1) * 8;
    const int b_ro = (sel >> 1) * 8 + lr, b_co = (sel & 1) * 8;

    float c[2][8][4];
    #pragma unroll
    for (int mi = 0; mi < 2; mi++)
        #pragma unroll
        for (int ni = 0; ni < 8; ni++)
            #pragma unroll
            for (int q = 0; q < 4; q++) c[mi][ni][q] = 0.f;

    for (int it = 0; it < NIT; ++it) {
        if (it <= NIT - 3) cp_wait<2>();
        else if (it == NIT - 2) cp_wait<1>();
        else cp_wait<0>();
        __syncthreads();

        const int ch = it / 3, tau = it % 3;
        const int aIdx = 2 * ch + (tau == 2 ? 1 : 0);   // A panel in use
        const int bIdx = 2 * ch + (tau >= 1 ? 1 : 0);   // B panel in use
        const uint32_t aBase = smem_u32(&Ar[(aIdx % 3) * TILE]);
        const uint32_t bBase = smem_u32(&Br[(bIdx % 3) * TILE]);

        #pragma unroll
        for (int ks = 0; ks < 4; ++ks) {
            uint32_t a[2][4];
            #pragma unroll
            for (int mi = 0; mi < 2; mi++) {
                uint32_t ad = aBase + 2 * ((wm * 32 + mi * 16 + a_ro) * LD + ks * 16 + a_co);
                ldmat_x4(a[mi][0], a[mi][1], a[mi][2], a[mi][3], ad);
            }
            uint32_t b[8][2];
            #pragma unroll
            for (int nj = 0; nj < 4; nj++) {
                uint32_t bd = bBase + 2 * ((wn * 64 + nj * 16 + b_ro) * LD + ks * 16 + b_co);
                ldmat_x4(b[nj * 2][0], b[nj * 2][1], b[nj * 2 + 1][0], b[nj * 2 + 1][1], bd);
            }
            #pragma unroll
            for (int mi = 0; mi < 2; mi++)
                #pragma unroll
                for (int ni = 0; ni < 8; ni++)
                    mma_bf16(c[mi][ni], a[mi], b[ni]);
        }

        __syncthreads();
        if (it + 3 < NIT) stageEvent(it + 3);
    }

    #pragma unroll
    for (int mi = 0; mi < 2; mi++) {
        const int m = m0 + wm * 32 + mi * 16 + lane / 4;
        #pragma unroll
        for (int ni = 0; ni < 8; ni++) {
            const int n = n0 + wn * 64 + ni * 8 + (lane & 3) * 2;
            const float2 bb = *reinterpret_cast<const float2*>(&bias[n]);
            float2 v0 = { c[mi][ni][0] + bb.x, c[mi][ni][1] + bb.y };
            float2 v1 = { c[mi][ni][2] + bb.x, c[mi][ni][3] + bb.y };
            *reinterpret_cast<float2*>(&C[(size_t)m * GG + n]) = v0;
            *reinterpret_cast<float2*>(&C[(size_t)(m + 8) * GG + n]) = v1;
        }
    }
}

// ---------------- GRU scan (register-stationary weights, 2-way K-split) ----
// EXACT round-9 version (best measured). Register-free xw staging via 4B
// cp.async into double-buffered smem; act threads read xw from smem;
// 2 barriers/step.
template <int R, bool STORE_SEQ>
__global__ void __launch_bounds__(768) gru_scan(
    const float* __restrict__ xw_f, const float* __restrict__ xw_b,
    const float* __restrict__ Whh_f, const float* __restrict__ Whh_b,
    const float* __restrict__ bhh_f, const float* __restrict__ bhh_b,
    __nv_bfloat16* __restrict__ out_hi, __nv_bfloat16* __restrict__ out_lo,
    float* __restrict__ out_final) {
    __shared__ __align__(16) float hsm[R][HH];
    __shared__ float psm[6][R][HH];
    __shared__ float xsm[2][R][GG];

    const int tid = threadIdx.x;
    const int u = tid & 127;
    const int grp = tid >> 7;         // 0..5
    const int g = grp % 3, ks = grp / 3;
    const int dir = blockIdx.y;
    const int b0 = blockIdx.x * R;

    const float* xw  = dir ? xw_b  : xw_f;
    const float* Whh = dir ? Whh_b : Whh_f;
    const float* bhh = dir ? bhh_b : bhh_f;

    // staging assignment: element e = tid + 768*k of [R*GG]; row/col fixed per thread
    constexpr int NE = (R * GG) / 768;       // R=2 -> 1, R=4 -> 2
    const int me = tid / GG;                 // 0..1
    const int je = tid % GG;

    ulonglong2 wreg[16];
    {
        const ulonglong2* wp = reinterpret_cast<const ulonglong2*>(
            Whh + (size_t)(g * 128 + u) * 128 + ks * 64);
        #pragma unroll
        for (int i = 0; i < 16; i++) wreg[i] = wp[i];
    }
    for (int i = tid; i < R * HH; i += 768) (&hsm[0][0])[i] = 0.f;

    const bool act = tid < R * 128;
    const int am = tid >> 7, au = u;
    float bR = 0.f, bZ = 0.f, bN = 0.f;
    if (act) { bR = bhh[au]; bZ = bhh[128 + au]; bN = bhh[256 + au]; }

    // stage xw for step 0 into buf 0
    {
        const int t0 = dir ? TT - 1 : 0;
        #pragma unroll
        for (int k = 0; k < NE; ++k) {
            const int mm = me + 2 * k;
            cp_async4(&xsm[0][mm][je], xw + ((size_t)(b0 + mm) * TT + t0) * GG + je);
        }
        cp_commit();
    }
    cp_wait<0>();
    __syncthreads();

    for (int it = 0; it < TT; ++it) {
        const int t = dir ? (TT - 1 - it) : it;

        // issue staging for step it+1 into buf (it+1)&1 (no registers held)
        if (it + 1 < TT) {
            const int tn = dir ? (TT - 2 - it) : (it + 1);
            #pragma unroll
            for (int k = 0; k < NE; ++k) {
                const int mm = me + 2 * k;
                cp_async4(&xsm[(it + 1) & 1][mm][je],
                          xw + ((size_t)(b0 + mm) * TT + tn) * GG + je);
            }
        }
        cp_commit();

        ull acc[R];
        #pragma unroll
        for (int m = 0; m < R; ++m) acc[m] = 0ULL;

        #pragma unroll
        for (int kp = 0; kp < 16; ++kp) {
            const ulonglong2 w2 = wreg[kp];
            #pragma unroll
            for (int m = 0; m < R; ++m) {
                ulonglong2 h2 = *reinterpret_cast<const ulonglong2*>(&hsm[m][ks * 64 + kp * 4]);
                ffma2(acc[m], w2.x, h2.x);
                ffma2(acc[m], w2.y, h2.y);
            }
        }

        #pragma unroll
        for (int m = 0; m < R; ++m) psm[grp][m][u] = hsum2(acc[m]);
        cp_wait<1>();   // group issued at step it-1 (data for step it) complete
        __syncthreads();

        if (act) {
            const float* xp = &xsm[it & 1][am][0];
            float aR = psm[0][am][au] + psm[3][am][au];
            float aZ = psm[1][am][au] + psm[4][am][au];
            float aN = psm[2][am][au] + psm[5][am][au];
            float r = sigf(xp[au] + aR + bR);
            float z = sigf(xp[128 + au] + aZ + bZ);
            float n = tanhfast(xp[256 + au] + r * (aN + bN));
            float hn = n + z * (hsm[am][au] - n);
            hsm[am][au] = hn;
            if (STORE_SEQ) {
                __nv_bfloat16 hh = __float2bfloat16(hn);
                __nv_bfloat16 hl = __float2bfloat16(hn - __bfloat162float(hh));
                size_t o = ((size_t)(b0 + am) * TT + t) * (2 * HH) + dir * HH + au;
                out_hi[o] = hh;
                out_lo[o] = hl;
            }
        }
        __syncthreads();
    }

    if (!STORE_SEQ && act)
        out_final[(b0 + am) * HH + au] = hsm[am][au];
}

// ---------------- epilogue: layer-1 backward first step + ReLU + FC --------
__global__ void __launch_bounds__(128) final_kernel(
    const __nv_bfloat16* __restrict__ h0hi, const __nv_bfloat16* __restrict__ h0lo,
    const float* __restrict__ h1f,
    const float* __restrict__ Wih1b,  // [384][256]
    const float* __restrict__ bih, const float* __restrict__ bhh,
    const float* __restrict__ fc_w, const float* __restrict__ fc_b,
    float* __restrict__ out)          // [B,2]
{
    const int b = blockIdx.x, j = threadIdx.x;
    __shared__ __align__(16) float x1[256];
    __shared__ float red[2][128];

    const size_t base = ((size_t)b * TT + (TT - 1)) * 256;
    x1[j]       = __bfloat162float(h0hi[base + j])       + __bfloat162float(h0lo[base + j]);
    x1[j + 128] = __bfloat162float(h0hi[base + j + 128]) + __bfloat162float(h0lo[base + j + 128]);
    __syncthreads();

    ull acc[3] = {0ULL, 0ULL, 0ULL};
    #pragma unroll 4
    for (int k = 0; k < 256; k += 4) {
        ulonglong2 xv = *reinterpret_cast<const ulonglong2*>(&x1[k]);
        #pragma unroll
        for (int g = 0; g < 3; g++) {
            ulonglong2 wv = *reinterpret_cast<const ulonglong2*>(
                &Wih1b[(size_t)(g * 128 + j) * 256 + k]);
            ffma2(acc[g], wv.x, xv.x);
            ffma2(acc[g], wv.y, xv.y);
        }
    }
    float a0 = hsum2(acc[0]) + bih[j];
    float a1 = hsum2(acc[1]) + bih[j + 128];
    float a2 = hsum2(acc[2]) + bih[j + 256];

    float r = sigf(a0 + bhh[j]);
    float z = sigf(a1 + bhh[j + 128]);
    float n = tanhfast(a2 + r * bhh[j + 256]);
    float hbv = (1.f - z) * n;

    float af = fmaxf(h1f[b * HH + j], 0.f);
    float ab = fmaxf(hbv, 0.f);
    red[0][j] = af * fc_w[j]       + ab * fc_w[128 + j];
    red[1][j] = af * fc_w[256 + j] + ab * fc_w[256 + 128 + j];
    __syncthreads();
    for (int s = 64; s > 0; s >>= 1) {
        if (j < s) { red[0][j] += red[0][j + s]; red[1][j] += red[1][j + s]; }
        __syncthreads();
    }
    if (j < 2) out[b * 2 + j] = red[j][0] + fc_b[j];
}

// ---------------- launch ----------------------------------------------------
extern "C" void kernel_launch(void* const* d_in, const int* in_sizes, int n_in,
                              void* d_out, int out_size) {
    const float* x     = (const float*)d_in[0];
    const float* Wih0f = (const float*)d_in[1];
    const float* Whh0f = (const float*)d_in[2];
    const float* bih0f = (const float*)d_in[3];
    const float* bhh0f = (const float*)d_in[4];
    const float* Wih0b = (const float*)d_in[5];
    const float* Whh0b = (const float*)d_in[6];
    const float* bih0b = (const float*)d_in[7];
    const float* bhh0b = (const float*)d_in[8];
    const float* Wih1f = (const float*)d_in[9];
    const float* Whh1f = (const float*)d_in[10];
    const float* bih1f = (const float*)d_in[11];
    const float* bhh1f = (const float*)d_in[12];
    const float* Wih1b = (const float*)d_in[13];
    const float* Whh1b = (const float*)d_in[14];
    const float* bih1b = (const float*)d_in[15];
    const float* bhh1b = (const float*)d_in[16];
    const float* fc_w  = (const float*)d_in[17];
    const float* fc_b  = (const float*)d_in[18];
    float* out = (float*)d_out;

    float *xw0f, *xw0b, *xw1f, *h1f;
    __nv_bfloat16 *h0hi, *h0lo, *xhi, *xlo;
    __nv_bfloat16 *w0fhi, *w0flo, *w0bhi, *w0blo, *w1fhi, *w1flo;
    cudaGetSymbolAddress((void**)&xw0f, g_xw0f);
    cudaGetSymbolAddress((void**)&xw0b, g_xw0b);
    cudaGetSymbolAddress((void**)&xw1f, g_xw1f);
    cudaGetSymbolAddress((void**)&h0hi, g_h0hi);
    cudaGetSymbolAddress((void**)&h0lo, g_h0lo);
    cudaGetSymbolAddress((void**)&h1f,  g_h1f);
    cudaGetSymbolAddress((void**)&xhi,  g_xhi);
    cudaGetSymbolAddress((void**)&xlo,  g_xlo);
    cudaGetSymbolAddress((void**)&w0fhi, g_w0fhi);
    cudaGetSymbolAddress((void**)&w0flo, g_w0flo);
    cudaGetSymbolAddress((void**)&w0bhi, g_w0bhi);
    cudaGetSymbolAddress((void**)&w0blo, g_w0blo);
    cudaGetSymbolAddress((void**)&w1fhi, g_w1fhi);
    cudaGetSymbolAddress((void**)&w1flo, g_w1flo);

    const int SMEM_HM = 6 * 128 * 72 * 2;   // 110592 bytes (3-slot A + 3-slot B)
    cudaFuncSetAttribute((const void*)gemm_hmma<64, 2>,
                         cudaFuncAttributeMaxDynamicSharedMemorySize, SMEM_HM);
    cudaFuncSetAttribute((const void*)gemm_hmma<256, 1>,
                         cudaFuncAttributeMaxDynamicSharedMemorySize, SMEM_HM);

    // ---- bf16 hi/lo splits (x + input weights), single fused launch ----
    {
        const int n0 = BB * TT * 64;
        const int n1 = GG * 64, n2 = GG * 64, n3 = GG * 256;
        const int total = n0 + n1 + n2 + n3;
        split_bf16_multi<<<(total + 255) / 256, 256>>>(
            x, xhi, xlo, n0,
            Wih0f, w0fhi, w0flo, n1,
            Wih0b, w0bhi, w0blo, n2,
            Wih1f, w1fhi, w1flo, n3);
    }

    // ---- layer 0 input projections (both directions) on HMMA ----
    gemm_hmma<64, 2><<<dim3(6, (BB * TT) / 128), 256, SMEM_HM>>>(
        xhi, xlo, w0fhi, w0flo, bih0f, xw0f, w0bhi, w0blo, bih0b, xw0b);

    // ---- layer 0 scans (emit h0 as bf16 hi/lo) ----
    gru_scan<4, true><<<dim3(BB / 4, 2), 768>>>(
        xw0f, xw0b, Whh0f, Whh0b, bhh0f, bhh0b, h0hi, h0lo, nullptr);

    // ---- layer 1 forward projection on HMMA + scan ----
    gemm_hmma<256, 1><<<dim3(3, (BB * TT) / 128), 256, SMEM_HM>>>(
        h0hi, h0lo, w1fhi, w1flo, bih1f, xw1f, nullptr, nullptr, nullptr, nullptr);
    gru_scan<2, false><<<dim3(BB / 2, 1), 768>>>(
        xw1f, nullptr, Whh1f, nullptr, bhh1f, nullptr, nullptr, nullptr, h1f);

    // ---- layer-1 backward one-step + ReLU + FC head ----
    final_kernel<<<BB, 128>>>(h0hi, h0lo, h1f, Wih1b, bih1b, bhh1b, fc_w, fc_b, out);
}

// round 15
// speedup vs baseline: 1.0343x; 1.0343x over previous
#include <cuda_runtime.h>
#include <cuda_bf16.h>
#include <stdint.h>
#include <stddef.h>

#define BB 256
#define TT 512
#define HH 128
#define GG 384   /* 3*H */

typedef unsigned long long ull;

// ---------------- scratch (device globals; no allocation allowed) ----------
__device__ float g_xw0f[(size_t)BB * TT * GG];
__device__ float g_xw0b[(size_t)BB * TT * GG];
__device__ float g_xw1f[(size_t)BB * TT * GG];
__device__ __nv_bfloat16 g_h0hi[(size_t)BB * TT * 2 * HH];
__device__ __nv_bfloat16 g_h0lo[(size_t)BB * TT * 2 * HH];
__device__ float g_h1f [BB * HH];
__device__ __nv_bfloat16 g_xhi[(size_t)BB * TT * 64];
__device__ __nv_bfloat16 g_xlo[(size_t)BB * TT * 64];
__device__ __nv_bfloat16 g_w0fhi[GG * 64],  g_w0flo[GG * 64];
__device__ __nv_bfloat16 g_w0bhi[GG * 64],  g_w0blo[GG * 64];
__device__ __nv_bfloat16 g_w1fhi[GG * 256], g_w1flo[GG * 256];

// ---------------- small helpers --------------------------------------------
__device__ __forceinline__ void ffma2(ull &d, ull a, ull b) {
    asm("fma.rn.f32x2 %0, %1, %2, %0;" : "+l"(d) : "l"(a), "l"(b));
}
__device__ __forceinline__ float hsum2(ull v) {
    float lo, hi;
    asm("mov.b64 {%0,%1}, %2;" : "=f"(lo), "=f"(hi) : "l"(v));
    return lo + hi;
}
__device__ __forceinline__ float sigf(float x)     { return 1.f / (1.f + __expf(-x)); }
__device__ __forceinline__ float tanhfast(float x) { return 2.f / (1.f + __expf(-2.f * x)) - 1.f; }

__device__ __forceinline__ void cp_async16(void* smem, const void* gmem) {
    uint32_t s = (uint32_t)__cvta_generic_to_shared(smem);
    asm volatile("cp.async.cg.shared.global [%0], [%1], 16;" :: "r"(s), "l"(gmem));
}
__device__ __forceinline__ void cp_async4(void* smem, const void* gmem) {
    uint32_t s = (uint32_t)__cvta_generic_to_shared(smem);
    asm volatile("cp.async.ca.shared.global [%0], [%1], 4;" :: "r"(s), "l"(gmem));
}
__device__ __forceinline__ void cp_commit() { asm volatile("cp.async.commit_group;"); }
template <int N>
__device__ __forceinline__ void cp_wait() { asm volatile("cp.async.wait_group %0;" :: "n"(N)); }

__device__ __forceinline__ uint32_t smem_u32(const void* p) {
    return (uint32_t)__cvta_generic_to_shared(p);
}

__device__ __forceinline__ void ldmat_x4(uint32_t &r0, uint32_t &r1, uint32_t &r2,
                                         uint32_t &r3, uint32_t addr) {
    asm volatile("ldmatrix.sync.aligned.m8n8.x4.shared.b16 {%0,%1,%2,%3}, [%4];"
                 : "=r"(r0), "=r"(r1), "=r"(r2), "=r"(r3) : "r"(addr));
}
__device__ __forceinline__ void mma_bf16(float c[4], const uint32_t a[4],
                                         const uint32_t b[2]) {
    asm volatile(
        "mma.sync.aligned.m16n8k16.row.col.f32.bf16.bf16.f32 "
        "{%0,%1,%2,%3}, {%4,%5,%6,%7}, {%8,%9}, {%0,%1,%2,%3};"
        : "+f"(c[0]), "+f"(c[1]), "+f"(c[2]), "+f"(c[3])
        : "r"(a[0]), "r"(a[1]), "r"(a[2]), "r"(a[3]), "r"(b[0]), "r"(b[1]));
}

// ---------------- fused fp32 -> bf16 hi/lo split (4 tensors, 1 launch) -----
__global__ void split_bf16_multi(
    const float* __restrict__ s0, __nv_bfloat16* __restrict__ h0, __nv_bfloat16* __restrict__ l0, int n0,
    const float* __restrict__ s1, __nv_bfloat16* __restrict__ h1, __nv_bfloat16* __restrict__ l1, int n1,
    const float* __restrict__ s2, __nv_bfloat16* __restrict__ h2, __nv_bfloat16* __restrict__ l2, int n2,
    const float* __restrict__ s3, __nv_bfloat16* __restrict__ h3, __nv_bfloat16* __restrict__ l3, int n3) {
    int i = blockIdx.x * blockDim.x + threadIdx.x;
    const float* s; __nv_bfloat16 *hi, *lo;
    if (i < n0)                { s = s0 + i; hi = h0 + i; lo = l0 + i; }
    else if (i < n0 + n1)      { int j = i - n0;           s = s1 + j; hi = h1 + j; lo = l1 + j; }
    else if (i < n0 + n1 + n2) { int j = i - n0 - n1;      s = s2 + j; hi = h2 + j; lo = l2 + j; }
    else if (i < n0 + n1 + n2 + n3) { int j = i - n0 - n1 - n2; s = s3 + j; hi = h3 + j; lo = l3 + j; }
    else return;
    float v = *s;
    __nv_bfloat16 h = __float2bfloat16(v);
    *hi = h;
    *lo = __float2bfloat16(v - __bfloat162float(h));
}

// ---------------- HMMA GEMM (double-buffer, round-6 exact): K=64 path ------
template <int K, int NSETS>
__global__ void __launch_bounds__(256, 2) gemm_hmma_db(
    const __nv_bfloat16* __restrict__ Ahi, const __nv_bfloat16* __restrict__ Alo,
    const __nv_bfloat16* __restrict__ W0hi, const __nv_bfloat16* __restrict__ W0lo,
    const float* __restrict__ b0, float* __restrict__ C0,
    const __nv_bfloat16* __restrict__ W1hi, const __nv_bfloat16* __restrict__ W1lo,
    const float* __restrict__ b1, float* __restrict__ C1) {
    constexpr int NCH = K / 64;
    constexpr int NIT = 3 * NCH;
    constexpr int LD  = 72;
    constexpr int TILE = 128 * LD;

    extern __shared__ __nv_bfloat16 smh[];
    __nv_bfloat16* As = smh;
    __nv_bfloat16* Bs = smh + 2 * TILE;

    const int tid = threadIdx.x;
    const int wid = tid >> 5, lane = tid & 31;

    int bx = blockIdx.x;
    const __nv_bfloat16 *Whi = W0hi, *Wlo = W0lo;
    const float* bias = b0; float* C = C0;
    if (NSETS == 2 && bx >= 3) { Whi = W1hi; Wlo = W1lo; bias = b1; C = C1; bx -= 3; }
    const int n0 = bx * 128;
    const int m0 = blockIdx.y * 128;

    auto stage = [&](int it, int buf) {
        const int ch = it / 3, term = it % 3;
        const __nv_bfloat16* sA = (term == 2) ? Alo : Ahi;
        const __nv_bfloat16* sB = (term == 1) ? Wlo : Whi;
        #pragma unroll
        for (int r = 0; r < 4; r++) {
            int idx = tid + r * 256;
            int row = idx >> 3, c = (idx & 7) * 8;
            cp_async16(&As[buf * TILE + row * LD + c],
                       &sA[(size_t)(m0 + row) * K + ch * 64 + c]);
            cp_async16(&Bs[buf * TILE + row * LD + c],
                       &sB[(size_t)(n0 + row) * K + ch * 64 + c]);
        }
        cp_commit();
    };

    stage(0, 0);
    if (NIT > 1) stage(1, 1);

    const int wm = wid >> 1, wn = wid & 1;
    const int lr = lane & 7, sel = lane >> 3;
    const int a_ro = (sel & 1) * 8 + lr, a_co = (sel >> 1) * 8;
    const int b_ro = (sel >> 1) * 8 + lr, b_co = (sel & 1) * 8;

    float c[2][8][4];
    #pragma unroll
    for (int mi = 0; mi < 2; mi++)
        #pragma unroll
        for (int ni = 0; ni < 8; ni++)
            #pragma unroll
            for (int q = 0; q < 4; q++) c[mi][ni][q] = 0.f;

    for (int it = 0; it < NIT; ++it) {
        if (it + 1 < NIT) cp_wait<1>(); else cp_wait<0>();
        __syncthreads();
        const int buf = it & 1;
        const uint32_t aBase = smem_u32(&As[buf * TILE]);
        const uint32_t bBase = smem_u32(&Bs[buf * TILE]);

        #pragma unroll
        for (int ks = 0; ks < 4; ++ks) {
            uint32_t a[2][4];
            #pragma unroll
            for (int mi = 0; mi < 2; mi++) {
                uint32_t ad = aBase + 2 * ((wm * 32 + mi * 16 + a_ro) * LD + ks * 16 + a_co);
                ldmat_x4(a[mi][0], a[mi][1], a[mi][2], a[mi][3], ad);
            }
            uint32_t b[8][2];
            #pragma unroll
            for (int nj = 0; nj < 4; nj++) {
                uint32_t bd = bBase + 2 * ((wn * 64 + nj * 16 + b_ro) * LD + ks * 16 + b_co);
                ldmat_x4(b[nj * 2][0], b[nj * 2][1], b[nj * 2 + 1][0], b[nj * 2 + 1][1], bd);
            }
            #pragma unroll
            for (int mi = 0; mi < 2; mi++)
                #pragma unroll
                for (int ni = 0; ni < 8; ni++)
                    mma_bf16(c[mi][ni], a[mi], b[ni]);
        }

        __syncthreads();
        if (it + 2 < NIT) stage(it + 2, buf);
    }

    #pragma unroll
    for (int mi = 0; mi < 2; mi++) {
        const int m = m0 + wm * 32 + mi * 16 + lane / 4;
        #pragma unroll
        for (int ni = 0; ni < 8; ni++) {
            const int n = n0 + wn * 64 + ni * 8 + (lane & 3) * 2;
            const float2 bb = *reinterpret_cast<const float2*>(&bias[n]);
            float2 v0 = { c[mi][ni][0] + bb.x, c[mi][ni][1] + bb.y };
            float2 v1 = { c[mi][ni][2] + bb.x, c[mi][ni][3] + bb.y };
            *reinterpret_cast<float2*>(&C[(size_t)m * GG + n]) = v0;
            *reinterpret_cast<float2*>(&C[(size_t)(m + 8) * GG + n]) = v1;
        }
    }
}

// ---------------- HMMA GEMM (panel-reuse 3-slot ring): K=256 path ----------
// tau0: (Ahi,Blo)  tau1: (Ahi,Bhi)  tau2: (Alo,Bhi) -> 4 panels/chunk.
template <int K>
__global__ void __launch_bounds__(256, 2) gemm_hmma_ring(
    const __nv_bfloat16* __restrict__ Ahi, const __nv_bfloat16* __restrict__ Alo,
    const __nv_bfloat16* __restrict__ Whi, const __nv_bfloat16* __restrict__ Wlo,
    const float* __restrict__ bias, float* __restrict__ C) {
    constexpr int NCH = K / 64;
    constexpr int NIT = 3 * NCH;
    constexpr int LD  = 72;
    constexpr int TILE = 128 * LD;

    extern __shared__ __nv_bfloat16 smh[];
    __nv_bfloat16* Ar = smh;              // [3][TILE]
    __nv_bfloat16* Br = smh + 3 * TILE;   // [3][TILE]

    const int tid = threadIdx.x;
    const int wid = tid >> 5, lane = tid & 31;
    const int n0 = blockIdx.x * 128;
    const int m0 = blockIdx.y * 128;

    auto stageA = [&](int k) {
        const __nv_bfloat16* src = (k & 1) ? Alo : Ahi;
        const int ch = k >> 1, slot = k % 3;
        #pragma unroll
        for (int r = 0; r < 4; r++) {
            int idx = tid + r * 256;
            int row = idx >> 3, c = (idx & 7) * 8;
            cp_async16(&Ar[slot * TILE + row * LD + c],
                       &src[(size_t)(m0 + row) * K + ch * 64 + c]);
        }
    };
    auto stageB = [&](int k) {
        const __nv_bfloat16* src = (k & 1) ? Whi : Wlo;
        const int ch = k >> 1, slot = k % 3;
        #pragma unroll
        for (int r = 0; r < 4; r++) {
            int idx = tid + r * 256;
            int row = idx >> 3, c = (idx & 7) * 8;
            cp_async16(&Br[slot * TILE + row * LD + c],
                       &src[(size_t)(n0 + row) * K + ch * 64 + c]);
        }
    };
    auto stageEvent = [&](int j) {
        const int jp = j / 3, tau = j % 3;
        if (tau == 0)      { stageA(2 * jp); stageB(2 * jp); }
        else if (tau == 1) { stageB(2 * jp + 1); }
        else               { stageA(2 * jp + 1); }
        cp_commit();
    };

    stageEvent(0);
    stageEvent(1);
    stageEvent(2);

    const int wm = wid >> 1, wn = wid & 1;
    const int lr = lane & 7, sel = lane >> 3;
    const int a_ro = (sel & 1) * 8 + lr, a_co = (sel >> 1) * 8;
    const int b_ro = (sel >> 1) * 8 + lr, b_co = (sel & 1) * 8;

    float c[2][8][4];
    #pragma unroll
    for (int mi = 0; mi < 2; mi++)
        #pragma unroll
        for (int ni = 0; ni < 8; ni++)
            #pragma unroll
            for (int q = 0; q < 4; q++) c[mi][ni][q] = 0.f;

    for (int it = 0; it < NIT; ++it) {
        if (it <= NIT - 3) cp_wait<2>();
        else if (it == NIT - 2) cp_wait<1>();
        else cp_wait<0>();
        __syncthreads();

        const int ch = it / 3, tau = it % 3;
        const int aIdx = 2 * ch + (tau == 2 ? 1 : 0);
        const int bIdx = 2 * ch + (tau >= 1 ? 1 : 0);
        const uint32_t aBase = smem_u32(&Ar[(aIdx % 3) * TILE]);
        const uint32_t bBase = smem_u32(&Br[(bIdx % 3) * TILE]);

        #pragma unroll
        for (int ks = 0; ks < 4; ++ks) {
            uint32_t a[2][4];
            #pragma unroll
            for (int mi = 0; mi < 2; mi++) {
                uint32_t ad = aBase + 2 * ((wm * 32 + mi * 16 + a_ro) * LD + ks * 16 + a_co);
                ldmat_x4(a[mi][0], a[mi][1], a[mi][2], a[mi][3], ad);
            }
            uint32_t b[8][2];
            #pragma unroll
            for (int nj = 0; nj < 4; nj++) {
                uint32_t bd = bBase + 2 * ((wn * 64 + nj * 16 + b_ro) * LD + ks * 16 + b_co);
                ldmat_x4(b[nj * 2][0], b[nj * 2][1], b[nj * 2 + 1][0], b[nj * 2 + 1][1], bd);
            }
            #pragma unroll
            for (int mi = 0; mi < 2; mi++)
                #pragma unroll
                for (int ni = 0; ni < 8; ni++)
                    mma_bf16(c[mi][ni], a[mi], b[ni]);
        }

        __syncthreads();
        if (it + 3 < NIT) stageEvent(it + 3);
    }

    #pragma unroll
    for (int mi = 0; mi < 2; mi++) {
        const int m = m0 + wm * 32 + mi * 16 + lane / 4;
        #pragma unroll
        for (int ni = 0; ni < 8; ni++) {
            const int n = n0 + wn * 64 + ni * 8 + (lane & 3) * 2;
            const float2 bb = *reinterpret_cast<const float2*>(&bias[n]);
            float2 v0 = { c[mi][ni][0] + bb.x, c[mi][ni][1] + bb.y };
            float2 v1 = { c[mi][ni][2] + bb.x, c[mi][ni][3] + bb.y };
            *reinterpret_cast<float2*>(&C[(size_t)m * GG + n]) = v0;
            *reinterpret_cast<float2*>(&C[(size_t)(m + 8) * GG + n]) = v1;
        }
    }
}

// ---------------- GRU scan (register-stationary weights, 2-way K-split) ----
// EXACT round-9 version (best measured). Register-free xw staging via 4B
// cp.async into double-buffered smem; act threads read xw from smem;
// 2 barriers/step.
template <int R, bool STORE_SEQ>
__global__ void __launch_bounds__(768) gru_scan(
    const float* __restrict__ xw_f, const float* __restrict__ xw_b,
    const float* __restrict__ Whh_f, const float* __restrict__ Whh_b,
    const float* __restrict__ bhh_f, const float* __restrict__ bhh_b,
    __nv_bfloat16* __restrict__ out_hi, __nv_bfloat16* __restrict__ out_lo,
    float* __restrict__ out_final) {
    __shared__ __align__(16) float hsm[R][HH];
    __shared__ float psm[6][R][HH];
    __shared__ float xsm[2][R][GG];

    const int tid = threadIdx.x;
    const int u = tid & 127;
    const int grp = tid >> 7;         // 0..5
    const int g = grp % 3, ks = grp / 3;
    const int dir = blockIdx.y;
    const int b0 = blockIdx.x * R;

    const float* xw  = dir ? xw_b  : xw_f;
    const float* Whh = dir ? Whh_b : Whh_f;
    const float* bhh = dir ? bhh_b : bhh_f;

    constexpr int NE = (R * GG) / 768;       // R=2 -> 1, R=4 -> 2
    const int me = tid / GG;                 // 0..1
    const int je = tid % GG;

    ulonglong2 wreg[16];
    {
        const ulonglong2* wp = reinterpret_cast<const ulonglong2*>(
            Whh + (size_t)(g * 128 + u) * 128 + ks * 64);
        #pragma unroll
        for (int i = 0; i < 16; i++) wreg[i] = wp[i];
    }
    for (int i = tid; i < R * HH; i += 768) (&hsm[0][0])[i] = 0.f;

    const bool act = tid < R * 128;
    const int am = tid >> 7, au = u;
    float bR = 0.f, bZ = 0.f, bN = 0.f;
    if (act) { bR = bhh[au]; bZ = bhh[128 + au]; bN = bhh[256 + au]; }

    // stage xw for step 0 into buf 0
    {
        const int t0 = dir ? TT - 1 : 0;
        #pragma unroll
        for (int k = 0; k < NE; ++k) {
            const int mm = me + 2 * k;
            cp_async4(&xsm[0][mm][je], xw + ((size_t)(b0 + mm) * TT + t0) * GG + je);
        }
        cp_commit();
    }
    cp_wait<0>();
    __syncthreads();

    for (int it = 0; it < TT; ++it) {
        const int t = dir ? (TT - 1 - it) : it;

        if (it + 1 < TT) {
            const int tn = dir ? (TT - 2 - it) : (it + 1);
            #pragma unroll
            for (int k = 0; k < NE; ++k) {
                const int mm = me + 2 * k;
                cp_async4(&xsm[(it + 1) & 1][mm][je],
                          xw + ((size_t)(b0 + mm) * TT + tn) * GG + je);
            }
        }
        cp_commit();

        ull acc[R];
        #pragma unroll
        for (int m = 0; m < R; ++m) acc[m] = 0ULL;

        #pragma unroll
        for (int kp = 0; kp < 16; ++kp) {
            const ulonglong2 w2 = wreg[kp];
            #pragma unroll
            for (int m = 0; m < R; ++m) {
                ulonglong2 h2 = *reinterpret_cast<const ulonglong2*>(&hsm[m][ks * 64 + kp * 4]);
                ffma2(acc[m], w2.x, h2.x);
                ffma2(acc[m], w2.y, h2.y);
            }
        }

        #pragma unroll
        for (int m = 0; m < R; ++m) psm[grp][m][u] = hsum2(acc[m]);
        cp_wait<1>();   // group issued at step it-1 (data for step it) complete
        __syncthreads();

        if (act) {
            const float* xp = &xsm[it & 1][am][0];
            float aR = psm[0][am][au] + psm[3][am][au];
            float aZ = psm[1][am][au] + psm[4][am][au];
            float aN = psm[2][am][au] + psm[5][am][au];
            float r = sigf(xp[au] + aR + bR);
            float z = sigf(xp[128 + au] + aZ + bZ);
            float n = tanhfast(xp[256 + au] + r * (aN + bN));
            float hn = n + z * (hsm[am][au] - n);
            hsm[am][au] = hn;
            if (STORE_SEQ) {
                __nv_bfloat16 hh = __float2bfloat16(hn);
                __nv_bfloat16 hl = __float2bfloat16(hn - __bfloat162float(hh));
                size_t o = ((size_t)(b0 + am) * TT + t) * (2 * HH) + dir * HH + au;
                out_hi[o] = hh;
                out_lo[o] = hl;
            }
        }
        __syncthreads();
    }

    if (!STORE_SEQ && act)
        out_final[(b0 + am) * HH + au] = hsm[am][au];
}

// ---------------- epilogue: layer-1 backward first step + ReLU + FC --------
__global__ void __launch_bounds__(128) final_kernel(
    const __nv_bfloat16* __restrict__ h0hi, const __nv_bfloat16* __restrict__ h0lo,
    const float* __restrict__ h1f,
    const float* __restrict__ Wih1b,  // [384][256]
    const float* __restrict__ bih, const float* __restrict__ bhh,
    const float* __restrict__ fc_w, const float* __restrict__ fc_b,
    float* __restrict__ out)          // [B,2]
{
    const int b = blockIdx.x, j = threadIdx.x;
    __shared__ __align__(16) float x1[256];
    __shared__ float red[2][128];

    const size_t base = ((size_t)b * TT + (TT - 1)) * 256;
    x1[j]       = __bfloat162float(h0hi[base + j])       + __bfloat162float(h0lo[base + j]);
    x1[j + 128] = __bfloat162float(h0hi[base + j + 128]) + __bfloat162float(h0lo[base + j + 128]);
    __syncthreads();

    ull acc[3] = {0ULL, 0ULL, 0ULL};
    #pragma unroll 4
    for (int k = 0; k < 256; k += 4) {
        ulonglong2 xv = *reinterpret_cast<const ulonglong2*>(&x1[k]);
        #pragma unroll
        for (int g = 0; g < 3; g++) {
            ulonglong2 wv = *reinterpret_cast<const ulonglong2*>(
                &Wih1b[(size_t)(g * 128 + j) * 256 + k]);
            ffma2(acc[g], wv.x, xv.x);
            ffma2(acc[g], wv.y, xv.y);
        }
    }
    float a0 = hsum2(acc[0]) + bih[j];
    float a1 = hsum2(acc[1]) + bih[j + 128];
    float a2 = hsum2(acc[2]) + bih[j + 256];

    float r = sigf(a0 + bhh[j]);
    float z = sigf(a1 + bhh[j + 128]);
    float n = tanhfast(a2 + r * bhh[j + 256]);
    float hbv = (1.f - z) * n;

    float af = fmaxf(h1f[b * HH + j], 0.f);
    float ab = fmaxf(hbv, 0.f);
    red[0][j] = af * fc_w[j]       + ab * fc_w[128 + j];
    red[1][j] = af * fc_w[256 + j] + ab * fc_w[256 + 128 + j];
    __syncthreads();
    for (int s = 64; s > 0; s >>= 1) {
        if (j < s) { red[0][j] += red[0][j + s]; red[1][j] += red[1][j + s]; }
        __syncthreads();
    }
    if (j < 2) out[b * 2 + j] = red[j][0] + fc_b[j];
}

// ---------------- launch ----------------------------------------------------
extern "C" void kernel_launch(void* const* d_in, const int* in_sizes, int n_in,
                              void* d_out, int out_size) {
    const float* x     = (const float*)d_in[0];
    const float* Wih0f = (const float*)d_in[1];
    const float* Whh0f = (const float*)d_in[2];
    const float* bih0f = (const float*)d_in[3];
    const float* bhh0f = (const float*)d_in[4];
    const float* Wih0b = (const float*)d_in[5];
    const float* Whh0b = (const float*)d_in[6];
    const float* bih0b = (const float*)d_in[7];
    const float* bhh0b = (const float*)d_in[8];
    const float* Wih1f = (const float*)d_in[9];
    const float* Whh1f = (const float*)d_in[10];
    const float* bih1f = (const float*)d_in[11];
    const float* bhh1f = (const float*)d_in[12];
    const float* Wih1b = (const float*)d_in[13];
    const float* Whh1b = (const float*)d_in[14];
    const float* bih1b = (const float*)d_in[15];
    const float* bhh1b = (const float*)d_in[16];
    const float* fc_w  = (const float*)d_in[17];
    const float* fc_b  = (const float*)d_in[18];
    float* out = (float*)d_out;

    float *xw0f, *xw0b, *xw1f, *h1f;
    __nv_bfloat16 *h0hi, *h0lo, *xhi, *xlo;
    __nv_bfloat16 *w0fhi, *w0flo, *w0bhi, *w0blo, *w1fhi, *w1flo;
    cudaGetSymbolAddress((void**)&xw0f, g_xw0f);
    cudaGetSymbolAddress((void**)&xw0b, g_xw0b);
    cudaGetSymbolAddress((void**)&xw1f, g_xw1f);
    cudaGetSymbolAddress((void**)&h0hi, g_h0hi);
    cudaGetSymbolAddress((void**)&h0lo, g_h0lo);
    cudaGetSymbolAddress((void**)&h1f,  g_h1f);
    cudaGetSymbolAddress((void**)&xhi,  g_xhi);
    cudaGetSymbolAddress((void**)&xlo,  g_xlo);
    cudaGetSymbolAddress((void**)&w0fhi, g_w0fhi);
    cudaGetSymbolAddress((void**)&w0flo, g_w0flo);
    cudaGetSymbolAddress((void**)&w0bhi, g_w0bhi);
    cudaGetSymbolAddress((void**)&w0blo, g_w0blo);
    cudaGetSymbolAddress((void**)&w1fhi, g_w1fhi);
    cudaGetSymbolAddress((void**)&w1flo, g_w1flo);

    const int SMEM_DB   = 4 * 128 * 72 * 2;   // 73728  (2-buf A + 2-buf B)
    const int SMEM_RING = 6 * 128 * 72 * 2;   // 110592 (3-slot A + 3-slot B)
    cudaFuncSetAttribute((const void*)gemm_hmma_db<64, 2>,
                         cudaFuncAttributeMaxDynamicSharedMemorySize, SMEM_DB);
    cudaFuncSetAttribute((const void*)gemm_hmma_ring<256>,
                         cudaFuncAttributeMaxDynamicSharedMemorySize, SMEM_RING);

    // ---- bf16 hi/lo splits (x + input weights), single fused launch ----
    {
        const int n0 = BB * TT * 64;
        const int n1 = GG * 64, n2 = GG * 64, n3 = GG * 256;
        const int total = n0 + n1 + n2 + n3;
        split_bf16_multi<<<(total + 255) / 256, 256>>>(
            x, xhi, xlo, n0,
            Wih0f, w0fhi, w0flo, n1,
            Wih0b, w0bhi, w0blo, n2,
            Wih1f, w1fhi, w1flo, n3);
    }

    // ---- layer 0 input projections (both directions): double-buffer HMMA ----
    gemm_hmma_db<64, 2><<<dim3(6, (BB * TT) / 128), 256, SMEM_DB>>>(
        xhi, xlo, w0fhi, w0flo, bih0f, xw0f, w0bhi, w0blo, bih0b, xw0b);

    // ---- layer 0 scans (emit h0 as bf16 hi/lo) ----
    gru_scan<4, true><<<dim3(BB / 4, 2), 768>>>(
        xw0f, xw0b, Whh0f, Whh0b, bhh0f, bhh0b, h0hi, h0lo, nullptr);

    // ---- layer 1 forward projection: panel-reuse ring HMMA + scan ----
    gemm_hmma_ring<256><<<dim3(3, (BB * TT) / 128), 256, SMEM_RING>>>(
        h0hi, h0lo, w1fhi, w1flo, bih1f, xw1f);
    gru_scan<2, false><<<dim3(BB / 2, 1), 768>>>(
        xw1f, nullptr, Whh1f, nullptr, bhh1f, nullptr, nullptr, nullptr, h1f);

    // ---- layer-1 backward one-step + ReLU + FC head ----
    final_kernel<<<BB, 128>>>(h0hi, h0lo, h1f, Wih1b, bih1b, bhh1b, fc_w, fc_b, out);
}